// round 3
// baseline (speedup 1.0000x reference)
#include <cuda_runtime.h>
#include <math.h>

#define FULL 0xffffffffu

// Problem constants (fixed by the dataset):
//   D = 64 feature dim, K = 3 bases, C = 5 classes
// Inputs (metadata order):
//   0: u_feat  [NU,64] f32     1: v_feat [NI,64] f32
//   2: u_indices [E] i32       3: v_indices [E] i32
//   4: basis_weights [3,64]    5: weights_scalars [3,5]
//   6: user_bias [NU,5]        7: item_bias [NI,5]
// Output: softmax logits [E,5] f32

__global__ __launch_bounds__(256) void bilinear_mixture_kernel(
    const float* __restrict__ u_feat,
    const float* __restrict__ v_feat,
    const int*   __restrict__ u_idx,
    const int*   __restrict__ v_idx,
    const float* __restrict__ bw,     // [3][64]
    const float* __restrict__ ws,     // [3][5]
    const float* __restrict__ ubias,  // [NU][5]
    const float* __restrict__ ibias,  // [NI][5]
    float* __restrict__ out,          // [E][5]
    int E)
{
    // Per-warp staging: 32 edges x 5 classes
    __shared__ float s_out[8][160];

    const int warp = threadIdx.x >> 5;
    const int lane = threadIdx.x & 31;
    const int c8   = lane & 7;   // position within 8-lane edge group (also class id for c8<5)
    const int sub  = lane >> 3;  // which of 4 edges this group handles per round

    const long long tile = (long long)blockIdx.x * 8 + warp;  // 32 edges per warp
    const long long e0   = tile * 32;
    if (e0 >= (long long)E) return;

    // Basis weights in registers: lane's 8 feature dims are
    // d = 4*c8 .. 4*c8+3  and  d = 32 + 4*c8 .. +3
    const float4* bw4 = (const float4*)bw;  // [3][16] float4
    float4 wlo[3], whi[3];
#pragma unroll
    for (int k = 0; k < 3; k++) {
        wlo[k] = bw4[k * 16 + c8];
        whi[k] = bw4[k * 16 + 8 + c8];
    }
    // weights_scalars column for this lane's class
    float wsc0, wsc1, wsc2;
    {
        int c = (c8 < 5) ? c8 : 0;
        wsc0 = ws[0 * 5 + c];
        wsc1 = ws[1 * 5 + c];
        wsc2 = ws[2 * 5 + c];
    }

    // Coalesced index load for this warp's 32 edges
    long long e_l = e0 + lane;
    int ui = 0, vi = 0;
    if (e_l < (long long)E) { ui = u_idx[e_l]; vi = v_idx[e_l]; }

    // Pre-shuffle round 0's indices so loads issue immediately
    int uidx_n = __shfl_sync(FULL, ui, sub);
    int vidx_n = __shfl_sync(FULL, vi, sub);

#pragma unroll 1
    for (int r = 0; r < 8; r++) {
        const int el = r * 4 + sub;                 // edge slot 0..31 within tile
        const int uidx = uidx_n;
        const int vidx = vidx_n;

        const float4* ur = (const float4*)(u_feat + (size_t)uidx * 64);
        const float4* vr = (const float4*)(v_feat + (size_t)vidx * 64);
        // Each 8-lane group reads a full 256B row, coalesced in 128B segments
        float4 ua = ur[c8],     ub = ur[8 + c8];
        float4 va = vr[c8],     vb = vr[8 + c8];

        // Shuffle next round's indices while this round's loads are in flight
        if (r < 7) {
            const int eln = (r + 1) * 4 + sub;
            uidx_n = __shfl_sync(FULL, ui, eln);
            vidx_n = __shfl_sync(FULL, vi, eln);
        }

        float4 plo, phi;
        plo.x = ua.x * va.x; plo.y = ua.y * va.y;
        plo.z = ua.z * va.z; plo.w = ua.w * va.w;
        phi.x = ub.x * vb.x; phi.y = ub.y * vb.y;
        phi.z = ub.z * vb.z; phi.w = ub.w * vb.w;

        float s0, s1, s2;
        {
            s0 = plo.x * wlo[0].x;
            s0 = fmaf(plo.y, wlo[0].y, s0); s0 = fmaf(plo.z, wlo[0].z, s0);
            s0 = fmaf(plo.w, wlo[0].w, s0); s0 = fmaf(phi.x, whi[0].x, s0);
            s0 = fmaf(phi.y, whi[0].y, s0); s0 = fmaf(phi.z, whi[0].z, s0);
            s0 = fmaf(phi.w, whi[0].w, s0);

            s1 = plo.x * wlo[1].x;
            s1 = fmaf(plo.y, wlo[1].y, s1); s1 = fmaf(plo.z, wlo[1].z, s1);
            s1 = fmaf(plo.w, wlo[1].w, s1); s1 = fmaf(phi.x, whi[1].x, s1);
            s1 = fmaf(phi.y, whi[1].y, s1); s1 = fmaf(phi.z, whi[1].z, s1);
            s1 = fmaf(phi.w, whi[1].w, s1);

            s2 = plo.x * wlo[2].x;
            s2 = fmaf(plo.y, wlo[2].y, s2); s2 = fmaf(plo.z, wlo[2].z, s2);
            s2 = fmaf(plo.w, wlo[2].w, s2); s2 = fmaf(phi.x, whi[2].x, s2);
            s2 = fmaf(phi.y, whi[2].y, s2); s2 = fmaf(phi.z, whi[2].z, s2);
            s2 = fmaf(phi.w, whi[2].w, s2);
        }

        // 8-lane butterfly reduction (stays within the group: offsets touch only c8 bits)
#pragma unroll
        for (int off = 4; off > 0; off >>= 1) {
            s0 += __shfl_xor_sync(FULL, s0, off);
            s1 += __shfl_xor_sync(FULL, s1, off);
            s2 += __shfl_xor_sync(FULL, s2, off);
        }

        // Epilogue: lane c8<5 handles class c8
        float logit = -INFINITY;
        if (c8 < 5) {
            logit = s0 * wsc0;
            logit = fmaf(s1, wsc1, logit);
            logit = fmaf(s2, wsc2, logit);
            logit += ubias[(size_t)uidx * 5 + c8];
            logit += ibias[(size_t)vidx * 5 + c8];
        }
        // softmax over the 8-lane group (lanes 5-7 contribute -inf / 0)
        float m = logit;
#pragma unroll
        for (int off = 4; off > 0; off >>= 1)
            m = fmaxf(m, __shfl_xor_sync(FULL, m, off));
        float ex = (c8 < 5) ? __expf(logit - m) : 0.0f;
        float ssum = ex;
#pragma unroll
        for (int off = 4; off > 0; off >>= 1)
            ssum += __shfl_xor_sync(FULL, ssum, off);
        if (c8 < 5)
            s_out[warp][el * 5 + c8] = __fdividef(ex, ssum);
    }

    __syncwarp();

    // Coalesced write: 160 contiguous floats per warp
    const long long nf_ll = (long long)E * 5 - e0 * 5;
    const int nf = (nf_ll >= 160) ? 160 : (int)nf_ll;
    if (nf == 160) {
        const float4* s4 = (const float4*)s_out[warp];
        float4* o4 = (float4*)(out + e0 * 5);   // e0*5 floats = multiple of 160 -> 16B aligned
        o4[lane] = s4[lane];
        if (lane < 8) o4[32 + lane] = s4[32 + lane];
    } else {
        for (int i = lane; i < nf; i += 32)
            out[e0 * 5 + i] = s_out[warp][i];
    }
}

extern "C" void kernel_launch(void* const* d_in, const int* in_sizes, int n_in,
                              void* d_out, int out_size)
{
    const float* u_feat = (const float*)d_in[0];
    const float* v_feat = (const float*)d_in[1];
    const int*   u_idx  = (const int*)d_in[2];
    const int*   v_idx  = (const int*)d_in[3];
    const float* bw     = (const float*)d_in[4];
    const float* ws     = (const float*)d_in[5];
    const float* ubias  = (const float*)d_in[6];
    const float* ibias  = (const float*)d_in[7];
    float* out = (float*)d_out;

    const int E = in_sizes[2];
    // 256 edges per block (8 warps x 32 edges)
    const int grid = (E + 255) / 256;
    bilinear_mixture_kernel<<<grid, 256>>>(u_feat, v_feat, u_idx, v_idx,
                                           bw, ws, ubias, ibias, out, E);
}